// round 2
// baseline (speedup 1.0000x reference)
#include <cuda_runtime.h>
#include <stdint.h>

// Problem constants
#define BATCH   32
#define SEQ     512
#define HDIM    768
#define NSPANS  1024
#define MROWS   (BATCH * SEQ)   // 16384

// Scratch: P = last_hidden @ W1[0:768,:], Q = last_hidden @ W1[768:1536,:]
__device__ float g_P[(size_t)MROWS * HDIM];
__device__ float g_Q[(size_t)MROWS * HDIM];

// ---------------------------------------------------------------------------
// Kernel 1: fp32 SGEMM  C[z] = A[16384x768] * W1half[z][768x768]
//   blockIdx.x : N tile (0..5), blockIdx.y : M tile (0..127), blockIdx.z : P/Q
//   128x128 block tile, BK=16, 256 threads, 8x8 per-thread micro-tile
// ---------------------------------------------------------------------------
constexpr int BM = 128, BN = 128, BK = 16;

__global__ __launch_bounds__(256, 2)
void sgemm_pq(const float* __restrict__ A, const float* __restrict__ W1)
{
    __shared__ float As[BK][BM];   // transposed A tile
    __shared__ float Bs[BK][BN];

    const float* Bmat = W1 + (size_t)blockIdx.z * HDIM * HDIM; // rows 0.. or 768..
    float* C = blockIdx.z ? g_Q : g_P;

    const int tid = threadIdx.x;

    // global load mapping
    const int aRow  = tid >> 2;          // 0..63
    const int aCol4 = (tid & 3) * 4;     // 0,4,8,12
    const int bRow  = tid >> 5;          // 0..7
    const int bCol4 = (tid & 31) * 4;    // 0..124

    const float* Ablk = A + (size_t)(blockIdx.y * BM) * HDIM;
    const float* Bblk = Bmat + blockIdx.x * BN;

    const int tr = (tid >> 4) * 8;       // row base in tile (0..120)
    const int tc = (tid & 15) * 4;       // col base (0..60), second half at +64

    float acc[8][8];
    #pragma unroll
    for (int i = 0; i < 8; i++)
        #pragma unroll
        for (int j = 0; j < 8; j++) acc[i][j] = 0.f;

    for (int kt = 0; kt < HDIM; kt += BK) {
        // load A tile (128x16), store transposed
        #pragma unroll
        for (int p = 0; p < 2; p++) {
            float4 v = *(const float4*)(Ablk + (size_t)(aRow + p * 64) * HDIM + kt + aCol4);
            As[aCol4 + 0][aRow + p * 64] = v.x;
            As[aCol4 + 1][aRow + p * 64] = v.y;
            As[aCol4 + 2][aRow + p * 64] = v.z;
            As[aCol4 + 3][aRow + p * 64] = v.w;
        }
        // load B tile (16x128)
        #pragma unroll
        for (int p = 0; p < 2; p++) {
            float4 v = *(const float4*)(Bblk + (size_t)(kt + bRow + p * 8) * HDIM + bCol4);
            *(float4*)&Bs[bRow + p * 8][bCol4] = v;
        }
        __syncthreads();

        #pragma unroll
        for (int k = 0; k < BK; k++) {
            float ra[8], rb[8];
            #pragma unroll
            for (int i = 0; i < 8; i++) ra[i] = As[k][tr + i];
            #pragma unroll
            for (int j = 0; j < 4; j++) rb[j]     = Bs[k][tc + j];
            #pragma unroll
            for (int j = 0; j < 4; j++) rb[4 + j] = Bs[k][64 + tc + j];
            #pragma unroll
            for (int i = 0; i < 8; i++)
                #pragma unroll
                for (int j = 0; j < 8; j++)
                    acc[i][j] = fmaf(ra[i], rb[j], acc[i][j]);
        }
        __syncthreads();
    }

    // write back: rows blockIdx.y*128 + tr..tr+7, cols blockIdx.x*128 + {tc, 64+tc}
    #pragma unroll
    for (int i = 0; i < 8; i++) {
        size_t row = (size_t)blockIdx.y * BM + tr + i;
        float* crow = C + row * HDIM + blockIdx.x * BN;
        *(float4*)(crow + tc)      = make_float4(acc[i][0], acc[i][1], acc[i][2], acc[i][3]);
        *(float4*)(crow + 64 + tc) = make_float4(acc[i][4], acc[i][5], acc[i][6], acc[i][7]);
    }
}

// ---------------------------------------------------------------------------
// Kernel 2: per-span logits. One warp per span.
//   out[b,n] = b2 + sum_h relu(P[b,start,h] + Q[b,end,h] + b1[h]) * W2[h]
//   span_indices: int32 (JAX x64-disabled downcasts the requested int64)
// ---------------------------------------------------------------------------
__global__ __launch_bounds__(256)
void span_logits(const float* __restrict__ b1, const float* __restrict__ W2,
                 const float* __restrict__ b2, const int* __restrict__ spans,
                 float* __restrict__ out)
{
    const int g    = blockIdx.x * blockDim.x + threadIdx.x;
    const int warp = g >> 5;
    const int lane = g & 31;
    if (warp >= BATCH * NSPANS) return;

    const int b = warp / NSPANS;
    int s0 = spans[(size_t)warp * 2 + 0];
    int s1 = spans[(size_t)warp * 2 + 1];
    // defensive clamp: no-op for valid indices, prevents OOB if dtype surprises
    s0 = min(max(s0, 0), SEQ - 1);
    s1 = min(max(s1, 0), SEQ - 1);

    const float4* p   = (const float4*)(g_P + ((size_t)b * SEQ + (size_t)s0) * HDIM);
    const float4* q   = (const float4*)(g_Q + ((size_t)b * SEQ + (size_t)s1) * HDIM);
    const float4* b14 = (const float4*)b1;
    const float4* w24 = (const float4*)W2;

    float acc = 0.f;
    #pragma unroll
    for (int i = lane; i < HDIM / 4; i += 32) {
        float4 pv = p[i], qv = q[i], bv = b14[i], wv = w24[i];
        acc = fmaf(fmaxf(pv.x + qv.x + bv.x, 0.f), wv.x, acc);
        acc = fmaf(fmaxf(pv.y + qv.y + bv.y, 0.f), wv.y, acc);
        acc = fmaf(fmaxf(pv.z + qv.z + bv.z, 0.f), wv.z, acc);
        acc = fmaf(fmaxf(pv.w + qv.w + bv.w, 0.f), wv.w, acc);
    }
    #pragma unroll
    for (int o = 16; o > 0; o >>= 1)
        acc += __shfl_xor_sync(0xffffffff, acc, o);
    if (lane == 0) out[warp] = acc + b2[0];
}

// ---------------------------------------------------------------------------
// Launch. Inputs (metadata order):
//   0: last_hidden f32 [32,512,768]
//   1: W1          f32 [1536,768]
//   2: b1          f32 [768]
//   3: W2          f32 [768,1]
//   4: b2          f32 [1]
//   5: span_indices int32 [32,1024,2]   (JAX default x64-disabled)
// Output: f32 [32,1024]
// ---------------------------------------------------------------------------
extern "C" void kernel_launch(void* const* d_in, const int* in_sizes, int n_in,
                              void* d_out, int out_size)
{
    const float* lh    = (const float*)d_in[0];
    const float* W1    = (const float*)d_in[1];
    const float* b1    = (const float*)d_in[2];
    const float* W2    = (const float*)d_in[3];
    const float* b2    = (const float*)d_in[4];
    const int*   spans = (const int*)d_in[5];
    float* out = (float*)d_out;

    dim3 ggrid(HDIM / BN, MROWS / BM, 2);   // (6, 128, 2)
    sgemm_pq<<<ggrid, 256>>>(lh, W1);

    const int total_threads = BATCH * NSPANS * 32;   // one warp per span
    span_logits<<<total_threads / 256, 256>>>(b1, W2, b2, spans, out);
}

// round 4
// speedup vs baseline: 1.7232x; 1.7232x over previous
#include <cuda_runtime.h>
#include <cuda_bf16.h>
#include <stdint.h>

// ---------------------------------------------------------------------------
// Problem constants
// ---------------------------------------------------------------------------
#define BATCH   32
#define SEQ     512
#define HDIM    768
#define NSPANS  1024
#define MROWS   (BATCH * SEQ)      // 16384
#define NCOLS   (2 * HDIM)         // 1536  (P | Q fused along N)
#define KSPLIT  (3 * HDIM)         // 2304  (hi*hi | lo*hi | hi*lo segments)

// GEMM tiling
#define BM 128
#define BN 128
#define BKC 32                     // K per chunk
#define NKCH (KSPLIT / BKC)        // 72
#define ROWB 80                    // smem row stride in bytes (64 data + 16 pad)
#define STAGE_BYTES (2 * BM * ROWB)   // A tile + B tile = 20480

// ---------------------------------------------------------------------------
// Device scratch
// ---------------------------------------------------------------------------
__device__ float g_P[(size_t)MROWS * HDIM];
__device__ float g_Q[(size_t)MROWS * HDIM];
__device__ __nv_bfloat16 g_Abf[(size_t)MROWS * KSPLIT];   // [16384][2304]
__device__ __nv_bfloat16 g_Bbf[(size_t)NCOLS * KSPLIT];   // [1536][2304]

// ---------------------------------------------------------------------------
// helpers
// ---------------------------------------------------------------------------
__device__ __forceinline__ uint32_t smem_u32(const void* p) {
    uint32_t a;
    asm("{ .reg .u64 t; cvta.to.shared.u64 t, %1; cvt.u32.u64 %0, t; }" : "=r"(a) : "l"(p));
    return a;
}
#define CP_ASYNC16(dst_u32, src_ptr) \
    asm volatile("cp.async.cg.shared.global [%0], [%1], 16;" :: "r"(dst_u32), "l"(src_ptr) : "memory")
#define CP_COMMIT() asm volatile("cp.async.commit_group;" ::: "memory")
template <int N> __device__ __forceinline__ void cp_wait() {
    asm volatile("cp.async.wait_group %0;" :: "n"(N) : "memory");
}

__device__ __forceinline__ void mma_bf16(float* c, const uint32_t* a, const uint32_t* b) {
    asm volatile(
        "mma.sync.aligned.m16n8k16.row.col.f32.bf16.bf16.f32 "
        "{%0,%1,%2,%3}, {%4,%5,%6,%7}, {%8,%9}, {%0,%1,%2,%3};"
        : "+f"(c[0]), "+f"(c[1]), "+f"(c[2]), "+f"(c[3])
        : "r"(a[0]), "r"(a[1]), "r"(a[2]), "r"(a[3]), "r"(b[0]), "r"(b[1]));
}

// ---------------------------------------------------------------------------
// Kernel 0a: fp32 -> bf16 hi/lo split for A (last_hidden), K-segments:
//   seg0 = hi, seg1 = lo, seg2 = hi    (pairs with B: hi, hi, lo)
// ---------------------------------------------------------------------------
__global__ __launch_bounds__(256)
void convert_A(const float* __restrict__ A)
{
    int idx = blockIdx.x * blockDim.x + threadIdx.x;
    if (idx >= MROWS * (HDIM / 2)) return;
    int m  = idx / (HDIM / 2);
    int k2 = (idx - m * (HDIM / 2)) * 2;
    float2 x = *(const float2*)(A + (size_t)m * HDIM + k2);
    __nv_bfloat16 h0 = __float2bfloat16(x.x), h1 = __float2bfloat16(x.y);
    __nv_bfloat16 l0 = __float2bfloat16(x.x - __bfloat162float(h0));
    __nv_bfloat16 l1 = __float2bfloat16(x.y - __bfloat162float(h1));
    __nv_bfloat16* row = g_Abf + (size_t)m * KSPLIT;
    __nv_bfloat162 hv; hv.x = h0; hv.y = h1;
    __nv_bfloat162 lv; lv.x = l0; lv.y = l1;
    *(__nv_bfloat162*)(row + k2)            = hv;
    *(__nv_bfloat162*)(row + HDIM + k2)     = lv;
    *(__nv_bfloat162*)(row + 2 * HDIM + k2) = hv;
}

// ---------------------------------------------------------------------------
// Kernel 0b: W1 -> transposed bf16 hi/lo. Bbf[n][k] (K-major, n = output col)
//   n < 768: P half uses W1 rows [0,768);  n >= 768: Q half uses rows [768,1536)
//   seg0 = hi, seg1 = hi, seg2 = lo
// ---------------------------------------------------------------------------
__global__ __launch_bounds__(256)
void convert_B(const float* __restrict__ W1)
{
    int idx = blockIdx.x * blockDim.x + threadIdx.x;
    if (idx >= NCOLS * (HDIM / 2)) return;
    int n  = idx / (HDIM / 2);
    int k2 = (idx - n * (HDIM / 2)) * 2;
    int h    = (n < HDIM) ? n : (n - HDIM);
    int doff = (n < HDIM) ? 0 : HDIM;
    float x0 = W1[(size_t)(doff + k2)     * HDIM + h];
    float x1 = W1[(size_t)(doff + k2 + 1) * HDIM + h];
    __nv_bfloat16 h0 = __float2bfloat16(x0), h1 = __float2bfloat16(x1);
    __nv_bfloat16 l0 = __float2bfloat16(x0 - __bfloat162float(h0));
    __nv_bfloat16 l1 = __float2bfloat16(x1 - __bfloat162float(h1));
    __nv_bfloat16* row = g_Bbf + (size_t)n * KSPLIT;
    __nv_bfloat162 hv; hv.x = h0; hv.y = h1;
    __nv_bfloat162 lv; lv.x = l0; lv.y = l1;
    *(__nv_bfloat162*)(row + k2)            = hv;
    *(__nv_bfloat162*)(row + HDIM + k2)     = hv;
    *(__nv_bfloat162*)(row + 2 * HDIM + k2) = lv;
}

// ---------------------------------------------------------------------------
// Kernel 1: HMMA bf16 GEMM  C[16384 x 1536] = Abf @ Bbf^T  (K = 2304)
//   grid (12, 128): bx = N tile (128 cols), by = M tile (128 rows)
//   256 threads = 8 warps in 2(M) x 4(N); warp tile 64x32; mma.m16n8k16
//   double-buffered cp.async; smem rows padded to 80 B -> conflict-free LDS
// ---------------------------------------------------------------------------
__global__ __launch_bounds__(256, 2)
void gemm_bf16(int dummy)
{
    __shared__ __align__(16) char smem_buf[2][STAGE_BYTES];

    const int tid  = threadIdx.x;
    const int wid  = tid >> 5;
    const int lane = tid & 31;
    const int bx = blockIdx.x, by = blockIdx.y;

    const int wm = wid >> 2;          // 0..1  (M)
    const int wn = wid & 3;           // 0..3  (N)
    const int g   = lane >> 2;        // 0..7
    const int tig = lane & 3;         // 0..3

    const uint32_t sb = smem_u32(smem_buf);

    // global source bases
    const __nv_bfloat16* Asrc = g_Abf + (size_t)(by * BM) * KSPLIT;
    const __nv_bfloat16* Bsrc = g_Bbf + (size_t)(bx * BN) * KSPLIT;

    // per-thread fill mapping: 2 A chunks + 2 B chunks of 16 B
    const int e0 = tid, e1 = tid + 256;
    const int ar0 = e0 >> 2, ac0 = e0 & 3;
    const int ar1 = e1 >> 2, ac1 = e1 & 3;

    float acc[4][4][4];
    #pragma unroll
    for (int i = 0; i < 4; i++)
        #pragma unroll
        for (int j = 0; j < 4; j++)
            #pragma unroll
            for (int q = 0; q < 4; q++) acc[i][j][q] = 0.f;

    auto fill = [&](int stage, int kt) {
        uint32_t abase = sb + stage * STAGE_BYTES;
        uint32_t bbase = abase + BM * ROWB;
        const __nv_bfloat16* ak = Asrc + kt * BKC;
        const __nv_bfloat16* bk = Bsrc + kt * BKC;
        CP_ASYNC16(abase + ar0 * ROWB + ac0 * 16, ak + (size_t)ar0 * KSPLIT + ac0 * 8);
        CP_ASYNC16(abase + ar1 * ROWB + ac1 * 16, ak + (size_t)ar1 * KSPLIT + ac1 * 8);
        CP_ASYNC16(bbase + ar0 * ROWB + ac0 * 16, bk + (size_t)ar0 * KSPLIT + ac0 * 8);
        CP_ASYNC16(bbase + ar1 * ROWB + ac1 * 16, bk + (size_t)ar1 * KSPLIT + ac1 * 8);
    };

    fill(0, 0);
    CP_COMMIT();

    for (int kt = 0; kt < NKCH; kt++) {
        const int cur = kt & 1;
        if (kt + 1 < NKCH) {
            fill(cur ^ 1, kt + 1);
            CP_COMMIT();
            cp_wait<1>();
        } else {
            cp_wait<0>();
        }
        __syncthreads();

        const char* As = smem_buf[cur];
        const char* Bs = smem_buf[cur] + BM * ROWB;

        #pragma unroll
        for (int ks = 0; ks < 2; ks++) {
            const int kb = ks * 32 + tig * 4;   // byte offset in row
            uint32_t af[4][4], bf[4][2];
            #pragma unroll
            for (int i = 0; i < 4; i++) {
                const char* rp = As + (wm * 64 + i * 16 + g) * ROWB + kb;
                af[i][0] = *(const uint32_t*)(rp);
                af[i][1] = *(const uint32_t*)(rp + 8 * ROWB);
                af[i][2] = *(const uint32_t*)(rp + 16);
                af[i][3] = *(const uint32_t*)(rp + 8 * ROWB + 16);
            }
            #pragma unroll
            for (int j = 0; j < 4; j++) {
                const char* rp = Bs + (wn * 32 + j * 8 + g) * ROWB + kb;
                bf[j][0] = *(const uint32_t*)(rp);
                bf[j][1] = *(const uint32_t*)(rp + 16);
            }
            #pragma unroll
            for (int i = 0; i < 4; i++)
                #pragma unroll
                for (int j = 0; j < 4; j++)
                    mma_bf16(acc[i][j], af[i], bf[j]);
        }
        __syncthreads();
    }

    // ------ epilogue: direct float2 stores to g_P / g_Q -------------------
    float* Cout;
    int cbase;
    if (bx < 6) { Cout = g_P; cbase = bx * BN; }
    else        { Cout = g_Q; cbase = bx * BN - HDIM; }

    #pragma unroll
    for (int i = 0; i < 4; i++) {
        const size_t r0 = (size_t)by * BM + wm * 64 + i * 16 + g;
        #pragma unroll
        for (int j = 0; j < 4; j++) {
            const int col = cbase + wn * 32 + j * 8 + tig * 2;
            *(float2*)(Cout + r0 * HDIM + col)       = make_float2(acc[i][j][0], acc[i][j][1]);
            *(float2*)(Cout + (r0 + 8) * HDIM + col) = make_float2(acc[i][j][2], acc[i][j][3]);
        }
    }
}

// ---------------------------------------------------------------------------
// Kernel 2: per-span logits. One warp per span.
// ---------------------------------------------------------------------------
__global__ __launch_bounds__(256)
void span_logits(const float* __restrict__ b1, const float* __restrict__ W2,
                 const float* __restrict__ b2, const int* __restrict__ spans,
                 float* __restrict__ out)
{
    const int gidx = blockIdx.x * blockDim.x + threadIdx.x;
    const int warp = gidx >> 5;
    const int lane = gidx & 31;
    if (warp >= BATCH * NSPANS) return;

    const int b = warp / NSPANS;
    int s0 = spans[(size_t)warp * 2 + 0];
    int s1 = spans[(size_t)warp * 2 + 1];
    s0 = min(max(s0, 0), SEQ - 1);
    s1 = min(max(s1, 0), SEQ - 1);

    const float4* p   = (const float4*)(g_P + ((size_t)b * SEQ + (size_t)s0) * HDIM);
    const float4* q   = (const float4*)(g_Q + ((size_t)b * SEQ + (size_t)s1) * HDIM);
    const float4* b14 = (const float4*)b1;
    const float4* w24 = (const float4*)W2;

    float acc = 0.f;
    #pragma unroll
    for (int i = lane; i < HDIM / 4; i += 32) {
        float4 pv = p[i], qv = q[i], bv = b14[i], wv = w24[i];
        acc = fmaf(fmaxf(pv.x + qv.x + bv.x, 0.f), wv.x, acc);
        acc = fmaf(fmaxf(pv.y + qv.y + bv.y, 0.f), wv.y, acc);
        acc = fmaf(fmaxf(pv.z + qv.z + bv.z, 0.f), wv.z, acc);
        acc = fmaf(fmaxf(pv.w + qv.w + bv.w, 0.f), wv.w, acc);
    }
    #pragma unroll
    for (int o = 16; o > 0; o >>= 1)
        acc += __shfl_xor_sync(0xffffffff, acc, o);
    if (lane == 0) out[warp] = acc + b2[0];
}

// ---------------------------------------------------------------------------
// Launch
// ---------------------------------------------------------------------------
extern "C" void kernel_launch(void* const* d_in, const int* in_sizes, int n_in,
                              void* d_out, int out_size)
{
    const float* lh    = (const float*)d_in[0];
    const float* W1    = (const float*)d_in[1];
    const float* b1    = (const float*)d_in[2];
    const float* W2    = (const float*)d_in[3];
    const float* b2    = (const float*)d_in[4];
    const int*   spans = (const int*)d_in[5];
    float* out = (float*)d_out;

    {
        int na = MROWS * (HDIM / 2);
        convert_A<<<(na + 255) / 256, 256>>>(lh);
        int nb = NCOLS * (HDIM / 2);
        convert_B<<<(nb + 255) / 256, 256>>>(W1);
    }

    dim3 ggrid(NCOLS / BN, MROWS / BM);   // (12, 128)
    gemm_bf16<<<ggrid, 256>>>(0);

    const int total_threads = BATCH * NSPANS * 32;
    span_logits<<<total_threads / 256, 256>>>(b1, W2, b2, spans, out);
}